// round 11
// baseline (speedup 1.0000x reference)
#include <cuda_runtime.h>
#include <cuda_fp16.h>
#include <cstdint>

#define GROUPS  2048
#define NT      8      // 8 iters x 128 rows
#define SW      36     // smem row stride in words (72 halves)

__device__ __forceinline__ uint32_t pack2h(float lo, float hi) {
    __half2 h = __floats2half2_rn(lo, hi);
    return *reinterpret_cast<uint32_t*>(&h);
}

__device__ __forceinline__ void mma_f16(float& d0, float& d1, float& d2, float& d3,
                                        uint32_t a0, uint32_t a1, uint32_t a2, uint32_t a3,
                                        uint32_t b0, uint32_t b1) {
    asm volatile("mma.sync.aligned.m16n8k16.row.col.f32.f16.f16.f32 "
                 "{%0,%1,%2,%3}, {%4,%5,%6,%7}, {%8,%9}, {%0,%1,%2,%3};"
                 : "+f"(d0), "+f"(d1), "+f"(d2), "+f"(d3)
                 : "r"(a0), "r"(a1), "r"(a2), "r"(a3), "r"(b0), "r"(b1));
}

// One CTA per group, 256 threads, 8 warps, warp tile m16 x n64 (warp owns ALL
// 64 cols of its 16 rows). Layer-1 A-fragments are register permutations of
// layer-0 accumulators (C-frag layout == A-frag layout for m16n8k16) -> the
// hidden layer h NEVER touches shared memory. X double-buffered; ONE barrier
// per 128-row iteration. Both layers' weight frags in registers.
extern "C" __global__ void __launch_bounds__(256, 1) convnn_r11(
    const float* __restrict__ x,  const float* __restrict__ W0,
    const float* __restrict__ b0, const float* __restrict__ W1,
    const float* __restrict__ b1, float* __restrict__ out)
{
    __shared__ uint32_t sX[2][128 * SW];   // 2 x 18KB
    __shared__ float    sB0[64], sB1[64];

    const int g    = blockIdx.x;
    const int tid  = threadIdx.x;
    const int lane = tid & 31;
    const int warp = tid >> 5;
    const int gid  = lane >> 2;   // 0..7
    const int tig  = lane & 3;    // 0..3
    const int r0   = warp * 16 + gid;    // warp owns rows [warp*16, +16)

    // ---- stage W0/W1 (fp16) through sX[0]; every warp pulls ALL 8 j-subtiles ----
    uint32_t wf[2][8][4][2];   // [layer][j-subtile][k-chunk][2] = 128 regs
    {
        const int sr = tid >> 4;          // 0..15
        const int c4 = (tid & 15) << 2;   // 0,4,...,60
        #pragma unroll
        for (int layer = 0; layer < 2; layer++) {
            const float* W = (layer ? W1 : W0) + (size_t)g * 64 * 64;
            #pragma unroll
            for (int rr = 0; rr < 4; rr++) {
                const int row = sr + rr * 16;
                float4 w = *(const float4*)(W + (size_t)row * 64 + c4);
                *(uint2*)&sX[0][row * SW + (c4 >> 1)] =
                    make_uint2(pack2h(w.x, w.y), pack2h(w.z, w.w));
            }
            __syncthreads();
            #pragma unroll
            for (int s = 0; s < 8; s++) {
                const int jr = (s * 8 + gid) * SW;
                #pragma unroll
                for (int kc = 0; kc < 4; kc++) {
                    wf[layer][s][kc][0] = sX[0][jr + kc * 8 + tig];
                    wf[layer][s][kc][1] = sX[0][jr + kc * 8 + 4 + tig];
                }
            }
            __syncthreads();
        }
    }
    if (tid < 64)       sB0[tid]      = b0[(size_t)g * 64 + tid];
    else if (tid < 128) sB1[tid - 64] = b1[(size_t)g * 64 + (tid - 64)];

    // ---- stage tile 0 into sX[0]; prefetch tile 1 (packed) ----
    uint2 px[8];
    #pragma unroll
    for (int q = 0; q < 8; q++) {
        const int f = q * 256 + tid;          // float4 index (2048 per tile)
        const int row = f >> 4, c4 = (f & 15) << 2;
        float4 v = *(const float4*)(x + (size_t)f * 4);
        *(uint2*)&sX[0][row * SW + (c4 >> 1)] =
            make_uint2(pack2h(v.x, v.y), pack2h(v.z, v.w));
    }
    #pragma unroll
    for (int q = 0; q < 8; q++) {
        float4 v = *(const float4*)(x + (size_t)8192 + (size_t)(q * 256 + tid) * 4);
        px[q] = make_uint2(pack2h(v.x, v.y), pack2h(v.z, v.w));
    }
    __syncthreads();

    for (int it = 0; it < NT; it++) {
        const uint32_t* cur = sX[it & 1];
        uint32_t*       nxt = sX[(it + 1) & 1];

        // ===== layer 0: acc[s] = X * W0^T  (dup-free A reads) =====
        float acc[8][4];
        #pragma unroll
        for (int s = 0; s < 8; s++)
            #pragma unroll
            for (int i = 0; i < 4; i++) acc[s][i] = 0.f;

        #pragma unroll
        for (int kc = 0; kc < 4; kc++) {
            const int kw = kc * 8 + tig;
            const uint32_t a0 = cur[(r0)     * SW + kw];
            const uint32_t a1 = cur[(r0 + 8) * SW + kw];
            const uint32_t a2 = cur[(r0)     * SW + kw + 4];
            const uint32_t a3 = cur[(r0 + 8) * SW + kw + 4];
            #pragma unroll
            for (int s = 0; s < 8; s++)
                mma_f16(acc[s][0], acc[s][1], acc[s][2], acc[s][3],
                        a0, a1, a2, a3, wf[0][s][kc][0], wf[0][s][kc][1]);
        }

        // stage tile it+1 (written into the OTHER buffer; its previous readers
        // finished before the barrier at the end of iter it-1)
        if (it + 1 < NT) {
            #pragma unroll
            for (int q = 0; q < 8; q++) {
                const int f = q * 256 + tid;
                const int row = f >> 4, c4 = (f & 15) << 2;
                *(uint2*)&nxt[row * SW + (c4 >> 1)] = px[q];
            }
        }
        if (it + 2 < NT) {
            const float* xs = x + (size_t)(it + 2) * 8192;
            #pragma unroll
            for (int q = 0; q < 8; q++) {
                float4 v = *(const float4*)(xs + (size_t)(q * 256 + tid) * 4);
                px[q] = make_uint2(pack2h(v.x, v.y), pack2h(v.z, v.w));
            }
        }

        // ===== epilogue 0: bias + LeakyReLU, pack h into A-fragments =====
        // L1 A-frag chunk kc: a0/a1 from acc[2kc] (cols 16kc+2tig), a2/a3 from acc[2kc+1]
        uint32_t ha[4][4];
        #pragma unroll
        for (int s = 0; s < 8; s++) {
            const float2 bb = *(const float2*)&sB0[s * 8 + 2 * tig];
            float h00 = acc[s][0] + bb.x; h00 = (h00 > 0.f) ? h00 : 0.2f * h00;
            float h01 = acc[s][1] + bb.y; h01 = (h01 > 0.f) ? h01 : 0.2f * h01;
            float h10 = acc[s][2] + bb.x; h10 = (h10 > 0.f) ? h10 : 0.2f * h10;
            float h11 = acc[s][3] + bb.y; h11 = (h11 > 0.f) ? h11 : 0.2f * h11;
            ha[s >> 1][(s & 1) * 2 + 0] = pack2h(h00, h01);
            ha[s >> 1][(s & 1) * 2 + 1] = pack2h(h10, h11);
        }

        // ===== layer 1: acc[s] = h * W1^T  (A straight from registers) =====
        #pragma unroll
        for (int s = 0; s < 8; s++)
            #pragma unroll
            for (int i = 0; i < 4; i++) acc[s][i] = 0.f;

        #pragma unroll
        for (int kc = 0; kc < 4; kc++)
            #pragma unroll
            for (int s = 0; s < 8; s++)
                mma_f16(acc[s][0], acc[s][1], acc[s][2], acc[s][3],
                        ha[kc][0], ha[kc][1], ha[kc][2], ha[kc][3],
                        wf[1][s][kc][0], wf[1][s][kc][1]);

        // ===== epilogue 1: bias, 32B-sector float2 stores =====
        const int brow = it * 128 + r0;
        #pragma unroll
        for (int s = 0; s < 8; s++) {
            const int j = s * 8 + 2 * tig;
            const float2 bb = *(const float2*)&sB1[j];
            float2 v0 = make_float2(acc[s][0] + bb.x, acc[s][1] + bb.y);
            float2 v1 = make_float2(acc[s][2] + bb.x, acc[s][3] + bb.y);
            *(float2*)(out + ((size_t)brow       * GROUPS + g) * 64 + j) = v0;
            *(float2*)(out + ((size_t)(brow + 8) * GROUPS + g) * 64 + j) = v1;
        }

        __syncthreads();   // the only barrier: X(it) reads done; X(it+1) visible
    }
}

extern "C" void kernel_launch(void* const* d_in, const int* in_sizes, int n_in,
                              void* d_out, int out_size) {
    const float* x  = (const float*)d_in[0];
    const float* W0 = (const float*)d_in[1];
    const float* b0 = (const float*)d_in[2];
    const float* W1 = (const float*)d_in[3];
    const float* b1 = (const float*)d_in[4];
    float* out = (float*)d_out;

    convnn_r11<<<GROUPS, 256>>>(x, W0, b0, W1, b1, out);
}